// round 16
// baseline (speedup 1.0000x reference)
#include <cuda_runtime.h>
#include <cuda_bf16.h>
#define SROW 40
typedef unsigned int u32;

__device__ float g_q[16777216];
__device__ float g_k[16777216];
__device__ float g_v[16777216];
__device__ float g_ao[16777216];

__device__ __forceinline__ void ldsm4(u32* r, u32 a) {
    asm volatile("ldmatrix.sync.aligned.m8n8.x4.shared.b16 {%0,%1,%2,%3},[%4];"
        :"=r"(r[0]),"=r"(r[1]),"=r"(r[2]),"=r"(r[3]):"r"(a));
}
__device__ __forceinline__ void ldsm2(u32* r, u32 a) {
    asm volatile("ldmatrix.sync.aligned.m8n8.x2.shared.b16 {%0,%1},[%2];"
        :"=r"(r[0]),"=r"(r[1]):"r"(a));
}
__device__ __forceinline__ void mmab(float* c, const u32* a, const u32* b) {
    asm volatile("mma.sync.aligned.m16n8k16.row.col.f32.bf16.bf16.f32 "
        "{%0,%1,%2,%3},{%4,%5,%6,%7},{%8,%9},{%0,%1,%2,%3};"
        :"+f"(c[0]),"+f"(c[1]),"+f"(c[2]),"+f"(c[3])
        :"r"(a[0]),"r"(a[1]),"r"(a[2]),"r"(a[3]),"r"(b[0]),"r"(b[1]));
}

__device__ __forceinline__ void g2r(const float* gp, int k0, float4* r) {
    const int tid = threadIdx.x;
    for (int i = 0; i < 2; i++) {
        const int ch = tid + 256*i;
        const float* p = gp + (size_t)(ch>>2)*1024 + k0 + ((ch&3)<<3);
        r[2*i] = *(const float4*)(p);
        r[2*i+1] = *(const float4*)(p+4);
    }
}

__device__ __forceinline__ void r2s(const float4* r, __nv_bfloat16* H, __nv_bfloat16* L) {
    const int tid = threadIdx.x;
    for (int i = 0; i < 2; i++) {
        const int ch = tid + 256*i;
        const int off = (ch>>2)*SROW + ((ch&3)<<3);
        float v[8];
        *(float4*)(v) = r[2*i];
        *(float4*)(v+4) = r[2*i+1];
        __nv_bfloat16 hb[8], lb[8];
        for (int j = 0; j < 8; j++) {
            hb[j] = __float2bfloat16(v[j]);
            lb[j] = __float2bfloat16(v[j] - __bfloat162float(hb[j]));
        }
        *(uint4*)(H+off) = *(const uint4*)(hb);
        *(uint4*)(L+off) = *(const uint4*)(lb);
    }
}

__device__ __forceinline__ void mma_core(const float* A, const float* W, float c[4][4][4]) {
    __shared__ __align__(16) __nv_bfloat16 SA[2][128*SROW];
    __shared__ __align__(16) __nv_bfloat16 SB[2][128*SROW];
    const int lane = threadIdx.x & 31, wid = threadIdx.x >> 5;
    const int wm = wid >> 2, wn = wid & 3, l15 = lane & 15;
    u32 ab[2], bb[2];
    ab[0] = (u32)__cvta_generic_to_shared(SA[0]);
    ab[1] = (u32)__cvta_generic_to_shared(SA[1]);
    bb[0] = (u32)__cvta_generic_to_shared(SB[0]);
    bb[1] = (u32)__cvta_generic_to_shared(SB[1]);
    u32 ao[4], bo[4];
    for (int t = 0; t < 4; t++) {
        ao[t] = (u32)((wm*64 + t*16 + l15)*(SROW*2) + (lane>>4)*16);
        bo[t] = (u32)((wn*32 + t*8 + (l15&7))*(SROW*2) + ((l15>>3)&1)*16);
    }
    for (int a = 0; a < 4; a++)
        for (int b = 0; b < 4; b++)
            for (int k = 0; k < 4; k++) c[a][b][k] = 0.f;

    float4 ar[4], br[4];
    g2r(A, 0, ar);
    g2r(W, 0, br);
    r2s(ar, SA[0], SA[1]);
    r2s(br, SB[0], SB[1]);
    __syncthreads();

    for (int k0 = 0; k0 < 1024; k0 += 32) {
        const bool more = (k0 + 32) < 1024;
        if (more) { g2r(A, k0+32, ar); g2r(W, k0+32, br); }
        for (int pass = 0; pass < 3; pass++) {
            const u32 au = ab[pass == 2 ? 1 : 0];
            const u32 bu = bb[pass == 1 ? 1 : 0];
            for (int ks = 0; ks < 2; ks++) {
                u32 af[4][4], bf[4][2];
                for (int t = 0; t < 4; t++) ldsm4(af[t], au + ao[t] + ks*32);
                for (int t = 0; t < 4; t++) ldsm2(bf[t], bu + bo[t] + ks*32);
                for (int a = 0; a < 4; a++)
                    for (int b = 0; b < 4; b++) mmab(c[a][b], af[a], bf[b]);
            }
        }
        __syncthreads();
        if (more) {
            r2s(ar, SA[0], SA[1]);
            r2s(br, SB[0], SB[1]);
            __syncthreads();
        }
    }
}

template<int MODE>
__global__ __launch_bounds__(256) void gemm_kernel(const float* A, const float* W,
                                                   const float* bias, float* out)
{
    float c[4][4][4];
    const float* Ab = (MODE == 0) ? A : g_ao;
    mma_core(Ab + (size_t)blockIdx.y*131072, W + (size_t)blockIdx.x*131072, c);

    const int lane = threadIdx.x & 31, wid = threadIdx.x >> 5;
    const int m0 = blockIdx.y*128 + (wid>>2)*64, n0 = blockIdx.x*128 + (wid&3)*32;
    const int mr = lane >> 2, nc = (lane & 3)*2;
    for (int a = 0; a < 4; a++)
    for (int b = 0; b < 4; b++)
    for (int k = 0; k < 4; k++) {
        const int m = m0 + a*16 + mr + (k>>1)*8;
        const int n = n0 + b*8 + nc + (k&1);
        const float val = c[a][b][k];
        if (MODE == 1) { out[(size_t)m*1024 + n] = val + bias[n]; continue; }
        const int s = n >> 10, rem = n & 1023;
        const size_t idx = ((size_t)((m>>9)*16 + (rem>>6))*512 + (m&511))*64 + (rem&63);
        if (s == 0) g_q[idx] = val*0.125f;
        else if (s == 1) g_k[idx] = val;
        else g_v[idx] = val;
    }
}

#define ASM_BYTES ((64*68*3 + 64*64 + 64 + 256 + 192)*4)

__global__ __launch_bounds__(256) void attn_kernel(const float* mask)
{
    extern __shared__ float sm[];
    float* Qt = sm;
    float* Kt = Qt + 64*68;
    float* Vs = Kt + 64*68;
    float* Ss = Vs + 64*64;
    float* ms = Ss + 64*68;
    float* red = ms + 64;
    float* mrow = red + 256;
    float* lrow = mrow + 64;
    float* srow = lrow + 64;

    const int tid = threadIdx.x, bh = blockIdx.y;
    const int b = bh >> 4, h = bh & 15, q0 = blockIdx.x << 6;
    const float* Qg = g_q + ((size_t)bh*512 + q0)*64;
    const float* Kg = g_k + (size_t)bh*32768;
    const float* Vg = g_v + (size_t)bh*32768;
    const float* Mg = mask + (size_t)b*512;

    for (int t = tid; t < 1024; t += 256) {
        const int r = t >> 4, cs = (t & 15) << 2;
        const float4 q4 = *(const float4*)(Qg + r*64 + cs);
        Qt[(cs+0)*68+r] = q4.x; Qt[(cs+1)*68+r] = q4.y;
        Qt[(cs+2)*68+r] = q4.z; Qt[(cs+3)*68+r] = q4.w;
    }
    if (tid < 64) { mrow[tid] = -1e30f; lrow[tid] = 0.f; }

    float o[4][4];
    for (int i = 0; i < 4; i++) for (int j = 0; j < 4; j++) o[i][j] = 0.f;
    const int tq = tid >> 4, tk = tid & 15, r = tid >> 2, sg = tid & 3;

    for (int kt = 0; kt < 8; kt++) {
        __syncthreads();
        const float* Kp = Kg + kt*4096;
        for (int t = tid; t < 1024; t += 256) {
            const int rr = t >> 4, cs = (t & 15) << 2;
            const float4 k4 = *(const float4*)(Kp + rr*64 + cs);
            Kt[(cs+0)*68+rr] = k4.x; Kt[(cs+1)*68+rr] = k4.y;
            Kt[(cs+2)*68+rr] = k4.z; Kt[(cs+3)*68+rr] = k4.w;
        }
        const float4* Vp = (const float4*)(Vg + kt*4096);
        for (int t = tid; t < 1024; t += 256) ((float4*)Vs)[t] = Vp[t];
        if (tid < 64) ms[tid] = Mg[kt*64 + tid];
        __syncthreads();

        float s[4][4];
        for (int i = 0; i < 4; i++) for (int j = 0; j < 4; j++) s[i][j] = 0.f;
        for (int d = 0; d < 64; d++) {
            const float4 qa = *(const float4*)(Qt + d*68 + tq*4);
            const float4 kb = *(const float4*)(Kt + d*68 + tk*4);
            const float aa[4] = {qa.x, qa.y, qa.z, qa.w};
            const float bv[4] = {kb.x, kb.y, kb.z, kb.w};
            for (int i = 0; i < 4; i++)
                for (int j = 0; j < 4; j++) s[i][j] = fmaf(aa[i], bv[j], s[i][j]);
        }
        for (int i = 0; i < 4; i++)
            for (int j = 0; j < 4; j++)
                Ss[(tq*4+i)*68 + tk*4 + j] = s[i][j] + ms[tk*4 + j];
        __syncthreads();

        float* Sr = Ss + r*68 + sg*16;
        float lm = -1e30f;
        for (int j = 0; j < 16; j++) lm = fmaxf(lm, Sr[j]);
        red[r*4 + sg] = lm;
        __syncthreads();
        const float tmax = fmaxf(fmaxf(red[r*4], red[r*4+1]), fmaxf(red[r*4+2], red[r*4+3]));
        const float mprev = mrow[r];
        const float mnew = fmaxf(mprev, tmax);
        float ls = 0.f;
        for (int j = 0; j < 16; j++) { const float p = __expf(Sr[j] - mnew); Sr[j] = p; ls += p; }
        __syncthreads();
        red[r*4 + sg] = ls;
        __syncthreads();
        if (sg == 0) {
            const float ts = red[r*4] + red[r*4+1] + red[r*4+2] + red[r*4+3];
            const float sc = __expf(mprev - mnew);
            lrow[r] = lrow[r]*sc + ts;
            mrow[r] = mnew;
            srow[r] = sc;
        }
        __syncthreads();

        for (int i = 0; i < 4; i++) {
            const float sc = srow[tq*4 + i];
            for (int j = 0; j < 4; j++) o[i][j] *= sc;
        }
        for (int kk = 0; kk < 64; kk++) {
            const float4 vb = *(const float4*)(Vs + kk*64 + tk*4);
            const float vv[4] = {vb.x, vb.y, vb.z, vb.w};
            float pv[4];
            for (int i = 0; i < 4; i++) pv[i] = Ss[(tq*4+i)*68 + kk];
            for (int i = 0; i < 4; i++)
                for (int j = 0; j < 4; j++) o[i][j] = fmaf(pv[i], vv[j], o[i][j]);
        }
    }

    for (int i = 0; i < 4; i++) {
        const float inv = 1.f / lrow[tq*4 + i];
        float ov[4];
        for (int j = 0; j < 4; j++) ov[j] = o[i][j]*inv;
        float* dst = g_ao + ((size_t)(b*512 + q0 + tq*4 + i)*1024 + h*64 + tk*4);
        *(float4*)(dst) = *(const float4*)(ov);
    }
}

extern "C" void kernel_launch(void* const* d_in, const int* in_sizes, int n_in,
                              void* d_out, int out_size)
{
    const float* x = (const float*)d_in[0];
    const float* mask = (const float*)d_in[1];
    const float* Wqkv = (const float*)d_in[2];
    const float* Wproj = (const float*)d_in[3];
    const float* bproj = (const float*)d_in[4];
    float* out = (float*)d_out;

    cudaFuncSetAttribute(attn_kernel, cudaFuncAttributeMaxDynamicSharedMemorySize, ASM_BYTES);
    gemm_kernel<0><<<dim3(24, 128), 256>>>(x, Wqkv, bproj, out);
    attn_kernel<<<dim3(8, 512), 256, ASM_BYTES>>>(mask);
    gemm_kernel<1><<<dim3(8, 128), 256>>>(x, Wproj, bproj, out);
}